// round 9
// baseline (speedup 1.0000x reference)
#include <cuda_runtime.h>
#include <cstdint>

#define D_IN 64
#define D_EDGE 16
#define H 16
#define MAXN 102400
#define MAXE 3276800

// ---------------- static device scratch ----------------
__device__ float g_xm[MAXN * H + 64];    // x @ W_msg1[:64]
__device__ float g_sk1[MAXN * H + 64];   // x @ W_skip1 + b_skip1
__device__ float g_hm[MAXN * H + 64];    // h1 @ W_msg2[:16]
__device__ float g_agg2[MAXN * H + 64];  // conv2 partial (edge-const + skip2)
__device__ int   g_cur[MAXN];            // histogram -> local-exclusive prefix
__device__ int   g_bsum[512];            // scan block sums (exclusive)
__device__ int   g_done;                 // scan completion counter
__device__ int   g_rank[MAXE];           // within-dst rank (from hist atomic)
__device__ int2  g_se[MAXE];             // dst-sorted (src, eid)

// row start for node n (after scan): bsum[n>>9] + g_cur[n]  (global excl prefix)
__device__ __forceinline__ int row_start(int n) {
    return g_bsum[n >> 9] + g_cur[n];
}

#define HIST_EDGES 4096

// ---------------------------------------------------------------------------
// pass_a (side stream, overlaps hist/scan/scatter):
// per node: xm = x @ Wm1[:64], sk1 = x @ Wsk1 + b_sk1
// ---------------------------------------------------------------------------
__global__ void pass_a(const float* __restrict__ x,
                       const float* __restrict__ Wm1,
                       const float* __restrict__ Wsk1,
                       const float* __restrict__ bsk1,
                       int N) {
    __shared__ float sWm[D_IN * H];
    __shared__ float sWs[D_IN * H];
    __shared__ float sb[H];
    __shared__ float sx[16 * D_IN];
    int tid = threadIdx.x;
    for (int i = tid; i < D_IN * H; i += 256) { sWm[i] = Wm1[i]; sWs[i] = Wsk1[i]; }
    if (tid < H) sb[tid] = bsk1[tid];
    int nbase = blockIdx.x * 16;
    for (int i = tid; i < 16 * D_IN; i += 256) {
        int n = nbase + (i >> 6);
        sx[i] = (n < N) ? x[(size_t)n * D_IN + (i & 63)] : 0.f;
    }
    __syncthreads();
    int ln = tid >> 4, j = tid & 15;
    int n = nbase + ln;
    if (n >= N) return;
    const float* xr = &sx[ln * D_IN];
    float a = 0.f, s = sb[j];
#pragma unroll
    for (int k = 0; k < D_IN; k++) {
        float xv = xr[k];
        a = fmaf(xv, sWm[k * H + j], a);
        s = fmaf(xv, sWs[k * H + j], s);
    }
    int o = n * H + j;
    g_xm[o] = a;
    g_sk1[o] = s;
}

// ---------------------------------------------------------------------------
// k_hist: dst histogram; atomic return IS within-dst rank. 4 edges/thread
// per inner step (int4 dst load, int4 rank store, 4 atomics in flight).
// ---------------------------------------------------------------------------
__global__ void k_hist(const int* __restrict__ ei, int E) {
    int tid = threadIdx.x;
    int base = blockIdx.x * HIST_EDGES;
    const int* dsts = ei + (size_t)E;
#pragma unroll
    for (int i = 0; i < HIST_EDGES / (256 * 4); i++) {
        int e = base + i * 1024 + tid * 4;
        if (e + 3 < E) {
            int4 d4 = *reinterpret_cast<const int4*>(dsts + e);
            int r0 = atomicAdd(&g_cur[d4.x], 1);
            int r1 = atomicAdd(&g_cur[d4.y], 1);
            int r2 = atomicAdd(&g_cur[d4.z], 1);
            int r3 = atomicAdd(&g_cur[d4.w], 1);
            *reinterpret_cast<int4*>(g_rank + e) = make_int4(r0, r1, r2, r3);
        } else {
            for (int k = 0; k < 4 && e + k < E; k++)
                g_rank[e + k] = atomicAdd(&g_cur[dsts[e + k]], 1);
        }
    }
}

// ---------------------------------------------------------------------------
// k_scan: fused two-level exclusive scan (last-block-done trick)
// ---------------------------------------------------------------------------
__global__ void k_scan(int N) {
    __shared__ int s[2][512];
    __shared__ int s_last;
    int t = threadIdx.x;
    int i = blockIdx.x * 512 + t;
    int v = (i < N) ? g_cur[i] : 0;
    s[0][t] = v;
    __syncthreads();
    int a = 0;
#pragma unroll
    for (int off = 1; off < 512; off <<= 1) {
        int sr = a; a ^= 1;
        s[a][t] = s[sr][t] + ((t >= off) ? s[sr][t - off] : 0);
        __syncthreads();
    }
    int incl = s[a][t];
    if (i < N) g_cur[i] = incl - v;  // local exclusive
    if (t == 511) g_bsum[blockIdx.x] = incl;
    __threadfence();
    __syncthreads();
    if (t == 0) s_last = (atomicAdd(&g_done, 1) == (int)gridDim.x - 1);
    __syncthreads();
    if (!s_last) return;
    int nsb = gridDim.x;
    int bv = (t < nsb) ? g_bsum[t] : 0;
    s[0][t] = bv;
    __syncthreads();
    a = 0;
#pragma unroll
    for (int off = 1; off < 512; off <<= 1) {
        int sr = a; a ^= 1;
        s[a][t] = s[sr][t] + ((t >= off) ? s[sr][t - off] : 0);
        __syncthreads();
    }
    if (t < nsb) g_bsum[t] = s[a][t] - bv;
}

// ---------------------------------------------------------------------------
// k_scatter: atomic-free scatter, 4 edges per thread (MLP 4)
// ---------------------------------------------------------------------------
__global__ void k_scatter(const int* __restrict__ ei, int E) {
    int t = blockIdx.x * 256 + threadIdx.x;
    int e = t * 4;
    if (e + 3 < E) {
        int4 s4 = *reinterpret_cast<const int4*>(ei + e);
        int4 d4 = *reinterpret_cast<const int4*>(ei + (size_t)E + e);
        int4 r4 = *reinterpret_cast<const int4*>(g_rank + e);
        int c0 = __ldg(&g_cur[d4.x]);
        int c1 = __ldg(&g_cur[d4.y]);
        int c2 = __ldg(&g_cur[d4.z]);
        int c3 = __ldg(&g_cur[d4.w]);
        int p0 = g_bsum[d4.x >> 9] + c0 + r4.x;
        int p1 = g_bsum[d4.y >> 9] + c1 + r4.y;
        int p2 = g_bsum[d4.z >> 9] + c2 + r4.z;
        int p3 = g_bsum[d4.w >> 9] + c3 + r4.w;
        g_se[p0] = make_int2(s4.x, e);
        g_se[p1] = make_int2(s4.y, e + 1);
        g_se[p2] = make_int2(s4.z, e + 2);
        g_se[p3] = make_int2(s4.w, e + 3);
    } else {
        for (int k = 0; e + k < E && k < 4; k++) {
            int s = ei[e + k];
            int d = ei[(size_t)E + e + k];
            int p = g_bsum[d >> 9] + g_cur[d] + g_rank[e + k];
            g_se[p] = make_int2(s, e + k);
        }
    }
}

// ---------------------------------------------------------------------------
// pass_bc (fused conv1 + inter-layer): one warp per node.
// lanes: eslot = lane>>2 (8 parallel edges), c = lane&3 (f4 quarter)
// ---------------------------------------------------------------------------
__global__ void __launch_bounds__(256, 6)
pass_bc(const float* __restrict__ ea,
        const float* __restrict__ Wm1,
        const float* __restrict__ b1,
        const float* __restrict__ Wm2,
        const float* __restrict__ b2,
        const float* __restrict__ Wsk2,
        const float* __restrict__ bsk2,
        int N, int E) {
    __shared__ float sW1e[H * H];   // Wm1 rows 64..79
    __shared__ float sW2e[H * H];   // Wm2 rows 16..31
    __shared__ float sWm2[H * H];   // Wm2 rows 0..15
    __shared__ float sWs2[H * H];   // Wsk2
    __shared__ float sb1[H], sb2[H], sbs2[H];
    __shared__ float sS[8][48];     // per warp: Sx[0:16) Se[16:32) h1[32:48)
    int tid = threadIdx.x;
    sW1e[tid] = Wm1[D_IN * H + tid];
    sWm2[tid] = Wm2[tid];
    sW2e[tid] = Wm2[H * H + tid];
    sWs2[tid] = Wsk2[tid];
    if (tid < H) { sb1[tid] = b1[tid]; sb2[tid] = b2[tid]; sbs2[tid] = bsk2[tid]; }
    __syncthreads();

    int w = tid >> 5, lane = tid & 31;
    int n = blockIdx.x * 8 + w;
    if (n >= N) return;
    int r0 = row_start(n);
    int r1 = (n + 1 < N) ? row_start(n + 1) : E;
    int eslot = lane >> 2, c = lane & 3;

    float ax0 = 0.f, ax1 = 0.f, ax2 = 0.f, ax3 = 0.f;
    float ae0 = 0.f, ae1 = 0.f, ae2 = 0.f, ae3 = 0.f;
    int p = r0 + eslot;
    while (p + 24 < r1) {
        int2 s0 = g_se[p];
        int2 s1 = g_se[p + 8];
        int2 s2 = g_se[p + 16];
        int2 s3 = g_se[p + 24];
        float4 e0 = __ldcs((const float4*)ea + (size_t)s0.y * 4 + c);
        float4 e1 = __ldcs((const float4*)ea + (size_t)s1.y * 4 + c);
        float4 e2 = __ldcs((const float4*)ea + (size_t)s2.y * 4 + c);
        float4 e3 = __ldcs((const float4*)ea + (size_t)s3.y * 4 + c);
        float4 x0 = __ldg((const float4*)g_xm + (size_t)s0.x * 4 + c);
        float4 x1 = __ldg((const float4*)g_xm + (size_t)s1.x * 4 + c);
        float4 x2 = __ldg((const float4*)g_xm + (size_t)s2.x * 4 + c);
        float4 x3 = __ldg((const float4*)g_xm + (size_t)s3.x * 4 + c);
        ax0 += (x0.x + x1.x) + (x2.x + x3.x);
        ax1 += (x0.y + x1.y) + (x2.y + x3.y);
        ax2 += (x0.z + x1.z) + (x2.z + x3.z);
        ax3 += (x0.w + x1.w) + (x2.w + x3.w);
        ae0 += (e0.x + e1.x) + (e2.x + e3.x);
        ae1 += (e0.y + e1.y) + (e2.y + e3.y);
        ae2 += (e0.z + e1.z) + (e2.z + e3.z);
        ae3 += (e0.w + e1.w) + (e2.w + e3.w);
        p += 32;
    }
    while (p < r1) {
        int2 se = g_se[p];
        float4 e4 = __ldcs((const float4*)ea + (size_t)se.y * 4 + c);
        float4 x4 = __ldg((const float4*)g_xm + (size_t)se.x * 4 + c);
        ax0 += x4.x; ax1 += x4.y; ax2 += x4.z; ax3 += x4.w;
        ae0 += e4.x; ae1 += e4.y; ae2 += e4.z; ae3 += e4.w;
        p += 8;
    }
#pragma unroll
    for (int off = 4; off < 32; off <<= 1) {
        ax0 += __shfl_xor_sync(0xffffffffu, ax0, off);
        ax1 += __shfl_xor_sync(0xffffffffu, ax1, off);
        ax2 += __shfl_xor_sync(0xffffffffu, ax2, off);
        ax3 += __shfl_xor_sync(0xffffffffu, ax3, off);
        ae0 += __shfl_xor_sync(0xffffffffu, ae0, off);
        ae1 += __shfl_xor_sync(0xffffffffu, ae1, off);
        ae2 += __shfl_xor_sync(0xffffffffu, ae2, off);
        ae3 += __shfl_xor_sync(0xffffffffu, ae3, off);
    }
    if (eslot == 0) {
        float* S = sS[w];
        S[c * 4 + 0] = ax0; S[c * 4 + 1] = ax1; S[c * 4 + 2] = ax2; S[c * 4 + 3] = ax3;
        S[16 + c * 4 + 0] = ae0; S[16 + c * 4 + 1] = ae1; S[16 + c * 4 + 2] = ae2; S[16 + c * 4 + 3] = ae3;
    }
    __syncwarp();

    float deg = (float)(r1 - r0);
    if (lane < 16) {
        int j = lane;
        float a = sS[w][j] + deg * sb1[j] + g_sk1[n * H + j];
#pragma unroll
        for (int k = 0; k < H; k++) a = fmaf(sS[w][16 + k], sW1e[k * H + j], a);
        sS[w][32 + j] = fmaxf(a, 0.f);
    }
    __syncwarp();
    if (lane < 16) {
        int j = lane;
        float hm = 0.f;
        float a2 = deg * sb2[j] + sbs2[j];
#pragma unroll
        for (int k = 0; k < H; k++) {
            float hk = sS[w][32 + k];
            hm = fmaf(hk, sWm2[k * H + j], hm);
            a2 = fmaf(hk, sWs2[k * H + j], a2);
            a2 = fmaf(sS[w][16 + k], sW2e[k * H + j], a2);
        }
        g_hm[n * H + j] = hm;
        g_agg2[n * H + j] = a2;
    }
}

// ---------------------------------------------------------------------------
// pass_de (fused conv2-aggregate + lin3): one warp per node.
// ---------------------------------------------------------------------------
__global__ void __launch_bounds__(256, 6)
pass_de(const float* __restrict__ Wl3,
        const float* __restrict__ bl3,
        float* __restrict__ out, int N, int E) {
    __shared__ float sW[H * D_IN];
    __shared__ float sb[D_IN];
    __shared__ float sH[8][20];
    int tid = threadIdx.x;
    for (int i = tid; i < H * D_IN; i += 256) sW[i] = Wl3[i];
    if (tid < D_IN) sb[tid] = bl3[tid];
    __syncthreads();

    int w = tid >> 5, lane = tid & 31;
    int n = blockIdx.x * 8 + w;
    if (n >= N) return;
    int r0 = row_start(n);
    int r1 = (n + 1 < N) ? row_start(n + 1) : E;
    int eslot = lane >> 2, c = lane & 3;

    float a0 = 0.f, a1 = 0.f, a2 = 0.f, a3 = 0.f;
    int p = r0 + eslot;
    while (p + 24 < r1) {
        int s0 = g_se[p].x;
        int s1 = g_se[p + 8].x;
        int s2 = g_se[p + 16].x;
        int s3 = g_se[p + 24].x;
        float4 h0 = __ldg((const float4*)g_hm + (size_t)s0 * 4 + c);
        float4 h1 = __ldg((const float4*)g_hm + (size_t)s1 * 4 + c);
        float4 h2 = __ldg((const float4*)g_hm + (size_t)s2 * 4 + c);
        float4 h3 = __ldg((const float4*)g_hm + (size_t)s3 * 4 + c);
        a0 += (h0.x + h1.x) + (h2.x + h3.x);
        a1 += (h0.y + h1.y) + (h2.y + h3.y);
        a2 += (h0.z + h1.z) + (h2.z + h3.z);
        a3 += (h0.w + h1.w) + (h2.w + h3.w);
        p += 32;
    }
    while (p < r1) {
        int src = g_se[p].x;
        float4 h4 = __ldg((const float4*)g_hm + (size_t)src * 4 + c);
        a0 += h4.x; a1 += h4.y; a2 += h4.z; a3 += h4.w;
        p += 8;
    }
#pragma unroll
    for (int off = 4; off < 32; off <<= 1) {
        a0 += __shfl_xor_sync(0xffffffffu, a0, off);
        a1 += __shfl_xor_sync(0xffffffffu, a1, off);
        a2 += __shfl_xor_sync(0xffffffffu, a2, off);
        a3 += __shfl_xor_sync(0xffffffffu, a3, off);
    }
    if (eslot == 0) {
        int b = c * 4;
        const float* ag = &g_agg2[n * H];
        sH[w][b + 0] = a0 + ag[b + 0];
        sH[w][b + 1] = a1 + ag[b + 1];
        sH[w][b + 2] = a2 + ag[b + 2];
        sH[w][b + 3] = a3 + ag[b + 3];
    }
    __syncwarp();

    float acc0 = sb[lane], acc1 = sb[lane + 32];
#pragma unroll
    for (int k = 0; k < H; k++) {
        float hk = sH[w][k];
        acc0 = fmaf(hk, sW[k * D_IN + lane], acc0);
        acc1 = fmaf(hk, sW[k * D_IN + lane + 32], acc1);
    }
    out[(size_t)n * D_IN + lane] = acc0;
    out[(size_t)n * D_IN + lane + 32] = acc1;
}

// ---------------------------------------------------------------------------
extern "C" void kernel_launch(void* const* d_in, const int* in_sizes, int n_in,
                              void* d_out, int out_size) {
    const float* x    = (const float*)d_in[0];
    const int*   ei   = (const int*)d_in[1];
    const float* ea   = (const float*)d_in[2];
    const float* Wm1  = (const float*)d_in[3];
    const float* bm1  = (const float*)d_in[4];
    const float* Wsk1 = (const float*)d_in[5];
    const float* bsk1 = (const float*)d_in[6];
    const float* Wm2  = (const float*)d_in[7];
    const float* bm2  = (const float*)d_in[8];
    const float* Wsk2 = (const float*)d_in[9];
    const float* bsk2 = (const float*)d_in[10];
    const float* Wl3  = (const float*)d_in[11];
    const float* bl3  = (const float*)d_in[12];
    float* out = (float*)d_out;

    int N = in_sizes[0] / D_IN;
    int E = in_sizes[1] / 2;

    int ebl = (E + HIST_EDGES - 1) / HIST_EDGES;
    int nsb = (N + 511) / 512;

    static cudaStream_t s2 = nullptr;
    static cudaEvent_t ev_fork = nullptr, ev_join = nullptr;
    if (!s2) {
        cudaStreamCreateWithFlags(&s2, cudaStreamNonBlocking);
        cudaEventCreateWithFlags(&ev_fork, cudaEventDisableTiming);
        cudaEventCreateWithFlags(&ev_join, cudaEventDisableTiming);
    }

    void* cur_ptr = nullptr;
    void* done_ptr = nullptr;
    cudaGetSymbolAddress(&cur_ptr, g_cur);
    cudaGetSymbolAddress(&done_ptr, g_done);
    cudaMemsetAsync(cur_ptr, 0, (size_t)N * sizeof(int), 0);
    cudaMemsetAsync(done_ptr, 0, sizeof(int), 0);

    // fork: pass_a runs concurrently with hist/scan/scatter
    cudaEventRecord(ev_fork, 0);
    cudaStreamWaitEvent(s2, ev_fork, 0);
    pass_a<<<(N + 15) / 16, 256, 0, s2>>>(x, Wm1, Wsk1, bsk1, N);
    cudaEventRecord(ev_join, s2);

    k_hist<<<ebl, 256>>>(ei, E);
    k_scan<<<nsb, 512>>>(N);
    k_scatter<<<(E / 4 + 255) / 256 + 1, 256>>>(ei, E);

    cudaStreamWaitEvent(0, ev_join, 0);
    pass_bc<<<(N + 7) / 8, 256>>>(ea, Wm1, bm1, Wm2, bm2, Wsk2, bsk2, N, E);
    pass_de<<<(N + 7) / 8, 256>>>(Wl3, bl3, out, N, E);
}